// round 3
// baseline (speedup 1.0000x reference)
#include <cuda_runtime.h>

// Problem constants (from reference)
constexpr int POOL     = 7;
constexpr int NUM_ROIS = 300;
constexpr int H        = 200;
constexpr int Wf       = 200;
constexpr int C        = 512;
constexpr int C4       = C / 4;                   // 128 float4 per pixel
constexpr int CELLS    = POOL * POOL;             // 49
constexpr int TOTAL4   = NUM_ROIS * CELLS * C4;   // 1,881,600 float4 outputs

__global__ __launch_bounds__(256)
void roi_pool_kernel(const float4* __restrict__ feat4,
                     const int4*  __restrict__ rois,
                     float4*      __restrict__ out4)
{
    int tid = blockIdx.x * blockDim.x + threadIdx.x;
    if (tid >= TOTAL4) return;

    int c4   = tid & (C4 - 1);       // channel /4 (contiguous within warp)
    int rc   = tid >> 7;             // roi*49 + cell
    int roi  = rc / CELLS;
    int cell = rc - roi * CELLS;
    int py   = cell / POOL;
    int px   = cell - py * POOL;

    const int4 r = rois[roi];
    const int x0 = r.x, y0 = r.y, w = r.z, h = r.w;

    // Match reference: sy = py * (h/7), sx = px * (w/7) in fp32
    const float hs = (float)h / (float)POOL;
    const float ws = (float)w / (float)POOL;
    const float sy = (float)py * hs;
    const float sx = (float)px * ws;

    const int y_lo = (int)floorf(sy);
    const int x_lo = (int)floorf(sx);
    const int y_hi = min(y_lo + 1, h - 1);
    const int x_hi = min(x_lo + 1, w - 1);

    const float fy = sy - (float)y_lo;
    const float fx = sx - (float)x_lo;
    const float gy = 1.0f - fy;
    const float gx = 1.0f - fx;

    // Absolute pixel coordinates
    const int ay_lo = y0 + y_lo;
    const int ay_hi = y0 + y_hi;
    const int ax_lo = x0 + x_lo;
    const int ax_hi = x0 + x_hi;

    // float4 indices into the (H, W, C) feature map
    const int i00 = (ay_lo * Wf + ax_lo) * C4 + c4;
    const int i01 = (ay_lo * Wf + ax_hi) * C4 + c4;
    const int i10 = (ay_hi * Wf + ax_lo) * C4 + c4;
    const int i11 = (ay_hi * Wf + ax_hi) * C4 + c4;

    const float4 v00 = feat4[i00];
    const float4 v01 = feat4[i01];
    const float4 v10 = feat4[i10];
    const float4 v11 = feat4[i11];

    // Bilinear: (v00*gx + v01*fx)*gy + (v10*gx + v11*fx)*fy
    float4 o;
    o.x = (v00.x * gx + v01.x * fx) * gy + (v10.x * gx + v11.x * fx) * fy;
    o.y = (v00.y * gx + v01.y * fx) * gy + (v10.y * gx + v11.y * fx) * fy;
    o.z = (v00.z * gx + v01.z * fx) * gy + (v10.z * gx + v11.z * fx) * fy;
    o.w = (v00.w * gx + v01.w * fx) * gy + (v10.w * gx + v11.w * fx) * fy;

    out4[tid] = o;
}

extern "C" void kernel_launch(void* const* d_in, const int* in_sizes, int n_in,
                              void* d_out, int out_size)
{
    const float4* feat4 = (const float4*)d_in[0];   // (1, 200, 200, 512) f32
    const int4*   rois  = (const int4*)d_in[1];     // (1, 300, 4) int32
    float4*       out4  = (float4*)d_out;           // (1, 300, 7, 7, 512) f32

    constexpr int THREADS = 256;
    constexpr int BLOCKS  = (TOTAL4 + THREADS - 1) / THREADS;  // 7350
    roi_pool_kernel<<<BLOCKS, THREADS>>>(feat4, rois, out4);
}

// round 7
// speedup vs baseline: 1.1633x; 1.1633x over previous
#include <cuda_runtime.h>

// Problem constants (from reference)
constexpr int POOL     = 7;
constexpr int NUM_ROIS = 300;
constexpr int Wf       = 200;
constexpr int C        = 512;
constexpr int C4       = C / 4;                   // 128 float4 per pixel
constexpr int CELLS    = POOL * POOL;             // 49

// One warp handles HALF a channel (64 c4) of one (roi, cell).
// Each thread produces 2 output float4 (c4 and c4+32) -> 8 independent loads.
// Total warps = 300*49*2 = 29400 = 3675 blocks * 8 warps. No tail.

__device__ __forceinline__ float4 bilerp4(float4 a, float4 b, float4 c, float4 d,
                                          float gx, float fx, float gy, float fy)
{
    float4 o;
    o.x = (a.x * gx + b.x * fx) * gy + (c.x * gx + d.x * fx) * fy;
    o.y = (a.y * gx + b.y * fx) * gy + (c.y * gx + d.y * fx) * fy;
    o.z = (a.z * gx + b.z * fx) * gy + (c.z * gx + d.z * fx) * fy;
    o.w = (a.w * gx + b.w * fx) * gy + (c.w * gx + d.w * fx) * fy;
    return o;
}

__global__ __launch_bounds__(256)
void roi_pool_kernel(const float4* __restrict__ feat4,
                     const int4*  __restrict__ rois,
                     float4*      __restrict__ out4)
{
    const int gw   = (blockIdx.x * 256 + threadIdx.x) >> 5;  // global warp id
    const int lane = threadIdx.x & 31;

    const int cellIdx = gw >> 1;            // roi*49 + cell
    const int half    = gw & 1;             // which 64-c4 half
    const int roi     = cellIdx / CELLS;
    const int cell    = cellIdx - roi * CELLS;
    const int py      = cell / POOL;
    const int px      = cell - py * POOL;

    const int4 r = __ldg(&rois[roi]);
    const int x0 = r.x, y0 = r.y, w = r.z, h = r.w;

    // Match reference: sy = py * (h/7), sx = px * (w/7) in fp32
    const float hs = (float)h / (float)POOL;
    const float ws = (float)w / (float)POOL;
    const float sy = (float)py * hs;
    const float sx = (float)px * ws;

    const int y_lo = (int)floorf(sy);
    const int x_lo = (int)floorf(sx);
    const int y_hi = min(y_lo + 1, h - 1);
    const int x_hi = min(x_lo + 1, w - 1);

    const float fy = sy - (float)y_lo;
    const float fx = sx - (float)x_lo;
    const float gy = 1.0f - fy;
    const float gx = 1.0f - fx;

    // Absolute pixel base offsets (in float4 units)
    const int p00 = ((y0 + y_lo) * Wf + (x0 + x_lo)) * C4;
    const int p01 = ((y0 + y_lo) * Wf + (x0 + x_hi)) * C4;
    const int p10 = ((y0 + y_hi) * Wf + (x0 + x_lo)) * C4;
    const int p11 = ((y0 + y_hi) * Wf + (x0 + x_hi)) * C4;

    const int c4a = half * 64 + lane;       // first chunk
    const int c4b = c4a + 32;               // second chunk

    // 8 independent 16B loads — issue all before consuming
    const float4 a00 = feat4[p00 + c4a];
    const float4 a01 = feat4[p01 + c4a];
    const float4 a10 = feat4[p10 + c4a];
    const float4 a11 = feat4[p11 + c4a];
    const float4 b00 = feat4[p00 + c4b];
    const float4 b01 = feat4[p01 + c4b];
    const float4 b10 = feat4[p10 + c4b];
    const float4 b11 = feat4[p11 + c4b];

    const float4 oa = bilerp4(a00, a01, a10, a11, gx, fx, gy, fy);
    const float4 ob = bilerp4(b00, b01, b10, b11, gx, fx, gy, fy);

    // Streaming stores: output is write-once; keep feat resident in L2.
    const int obase = cellIdx * C4;
    __stcs(&out4[obase + c4a], oa);
    __stcs(&out4[obase + c4b], ob);
}

extern "C" void kernel_launch(void* const* d_in, const int* in_sizes, int n_in,
                              void* d_out, int out_size)
{
    const float4* feat4 = (const float4*)d_in[0];   // (1, 200, 200, 512) f32
    const int4*   rois  = (const int4*)d_in[1];     // (1, 300, 4) int32
    float4*       out4  = (float4*)d_out;           // (1, 300, 7, 7, 512) f32

    constexpr int BLOCKS = NUM_ROIS * CELLS * 2 / 8;  // 3675 blocks, 8 warps each
    roi_pool_kernel<<<BLOCKS, 256>>>(feat4, rois, out4);
}